// round 9
// baseline (speedup 1.0000x reference)
#include <cuda_runtime.h>
#include <cstdint>

#define BB 16
#define QQ 300
#define SNUM 16
#define HID 256
#define T_TOT 13125
#define W0 100
#define H0 100
#define QP 3
#define S_SCALE_C 0.077f

#define NBLK 384            // 96 row-groups x 4 out-groups
#define NTHR 256
#define RG 8                // rows per row-group (96*8 = 768)
#define OG 64               // outputs per out-group (4*64 = 256)
#define NROWS (BB * QP * SNUM)   // 768

__device__ float h1_glob[NROWS * HID];     // 786KB, post-tanh hidden layer
__device__ unsigned g_cnt;                 // cumulative ticket counter

typedef unsigned long long ull;

__device__ __forceinline__ ull pack2(float lo, float hi) {
    ull r; asm("mov.b64 %0, {%1, %2};" : "=l"(r) : "f"(lo), "f"(hi)); return r;
}
__device__ __forceinline__ void unpack2(ull v, float& lo, float& hi) {
    asm("mov.b64 {%0, %1}, %2;" : "=f"(lo), "=f"(hi) : "l"(v));
}
__device__ __forceinline__ void fma2(ull& d, ull a, ull b) {
    asm("fma.rn.f32x2 %0, %1, %2, %3;" : "=l"(d) : "l"(a), "l"(b), "l"(d));
}
__device__ __forceinline__ float tanh_fast(float x) {
    float r; asm("tanh.approx.f32 %0, %1;" : "=f"(r) : "f"(x)); return r;
}
__device__ __forceinline__ unsigned ld_cg_u32(const unsigned* p) {
    unsigned v; asm volatile("ld.global.cg.u32 %0, [%1];" : "=r"(v) : "l"(p)); return v;
}
__device__ __forceinline__ float ld_cg_f32(const float* p) {
    float v; asm volatile("ld.global.cg.f32 %0, [%1];" : "=f"(v) : "l"(p)); return v;
}

__device__ __forceinline__ void poly_xy(const float* __restrict__ c, int s,
                                        float& spx, float& spy) {
    const float t  = (float)s * (1.0f / (float)(SNUM - 1));
    const float t2 = t * t, t3 = t2 * t;
    spx = 2.0f * (c[0] * t3 + c[1] * t2 + c[2] * t + c[3] - 0.5f);
    spy = 2.0f * (c[4] * t3 + c[5] * t2 + c[6] * t + c[7] - 0.5f);
}

__global__ __launch_bounds__(NTHR, 3) void fused_kernel(
        const float* __restrict__ rp,
        const float* __restrict__ mem,
        const float* __restrict__ w1,
        const float* __restrict__ b1,
        const float* __restrict__ w2,
        const float* __restrict__ b2,
        const int* __restrict__ rl,
        float* __restrict__ out) {
    const int blk = blockIdx.x;
    const int tid = threadIdx.x;
    const int rg  = blk >> 2;          // row-group 0..95
    const int og  = blk & 3;           // out-group 0..3

    __shared__ __align__(16) float gsp[HID * RG];   // [c][r] 8KB
    __shared__ __align__(16) float offs[2][4];
    __shared__ int rls[QQ];
    __shared__ unsigned sh_tgt;

    // ============ Phase A1: gather 8 rows x 256 channels ============
    #pragma unroll
    for (int it = 0; it < RG * HID / NTHR; it++) {   // 8 iters
        const int e = it * NTHR + tid;               // 0..2047
        const int c = e & 255;
        const int r = e >> 8;                        // 0..7
        const int row = rg * RG + r;
        const int b   = row / (QP * SNUM);
        const int rem = row % (QP * SNUM);
        const int qp  = rem >> 4;
        const int s   = rem & 15;

        float gx, gy;
        poly_xy(rp + ((size_t)b * QQ + qp) * 8, s, gx, gy);
        const float x = (gx + 1.0f) * (W0 * 0.5f) - 0.5f;
        const float y = (gy + 1.0f) * (H0 * 0.5f) - 0.5f;
        const float x0f = floorf(x), y0f = floorf(y);
        const int x0 = (int)x0f, y0 = (int)y0f;
        const float wx1 = x - x0f, wx0 = 1.0f - wx1;
        const float wy1 = y - y0f, wy0 = 1.0f - wy1;

        const float* memb = mem + (size_t)b * T_TOT * HID + c;
        float a = 0.0f;
        #pragma unroll
        for (int dy = 0; dy < 2; dy++) {
            const int yi = y0 + dy;
            if (yi < 0 || yi >= H0) continue;
            const float wy = dy ? wy1 : wy0;
            #pragma unroll
            for (int dx = 0; dx < 2; dx++) {
                const int xi = x0 + dx;
                if (xi < 0 || xi >= W0) continue;
                a += wy * (dx ? wx1 : wx0) *
                     __ldg(memb + (size_t)(yi * W0 + xi) * HID);
            }
        }
        gsp[c * RG + r] = a;
    }
    __syncthreads();

    // ============ Phase A2: layer 1 tile [8 rows x 64 outs], full-c per thread ===
    {
        const int o  = tid & (OG - 1);       // 0..63
        const int pr = tid >> 6;             // row-pair 0..3
        const float* wc = w1 + og * OG + o;  // column o of this out-group
        const float* gp = &gsp[pr * 2];

        ull acc0 = 0, acc1 = 0;              // even / odd c chains
        #pragma unroll 8
        for (int c = 0; c < HID; c += 2) {
            const float wa = __ldg(wc + (size_t)c * HID);
            const float wb = __ldg(wc + (size_t)(c + 1) * HID);
            fma2(acc0, *reinterpret_cast<const ull*>(gp + c * RG), pack2(wa, wa));
            fma2(acc1, *reinterpret_cast<const ull*>(gp + (c + 1) * RG), pack2(wb, wb));
        }
        float e0, e1, o0, o1;
        unpack2(acc0, e0, e1);
        unpack2(acc1, o0, o1);
        const float bv = __ldg(&b1[og * OG + o]);
        const float h0 = tanh_fast(e0 + o0 + bv);
        const float h1v = tanh_fast(e1 + o1 + bv);
        const int row0 = rg * RG + pr * 2;
        h1_glob[(size_t)row0 * HID + og * OG + o]       = h0;
        h1_glob[(size_t)(row0 + 1) * HID + og * OG + o] = h1v;
    }
    __threadfence();
    __syncthreads();

    // arrive
    if (tid == 0) {
        const unsigned t = atomicAdd(&g_cnt, 1u);
        sh_tgt = t - (t % NBLK) + NBLK;
    }

    // ============ Phase C prologue: this block's b and rl slice (pre-spin) ========
    const int bC = blk / (NBLK / BB);            // 24 blocks per batch
    for (int t = tid; t < QQ; t += NTHR)
        rls[t] = rl[bC * QQ + t];

    // ============ global barrier ============
    __syncthreads();
    if (tid == 0) {
        const unsigned tgt = sh_tgt;
        while ((int)(ld_cg_u32(&g_cnt) - tgt) < 0)
            __nanosleep(32);
    }
    __syncthreads();
    __threadfence();                              // acquire

    // ============ Phase C1: layer 2 for rows 2*blk, 2*blk+1 -> offs[2][4] ========
    {
        const int w = tid >> 5, lane = tid & 31;  // 8 warps = 2 rows x 4 outs
        const int p = w >> 2, k = w & 3;
        const int rowp = 2 * blk + p;
        const float* h1r = h1_glob + (size_t)rowp * HID;
        float a = 0.0f;
        #pragma unroll
        for (int j = lane; j < HID; j += 32)
            a += ld_cg_f32(h1r + j) * __ldg(&w2[j * 4 + k]);
        #pragma unroll
        for (int o = 16; o > 0; o >>= 1)
            a += __shfl_xor_sync(0xffffffffu, a, o);
        if (lane == 0)
            offs[p][k] = S_SCALE_C * tanh_fast(a + __ldg(&b2[k]));
    }
    __syncthreads();

    // ============ Phase C2: scatter outputs for matching queries ============
    {
        const float4 off0 = *reinterpret_cast<const float4*>(&offs[0][0]);
        const float4 off1 = *reinterpret_cast<const float4*>(&offs[1][0]);
        const int row0 = 2 * blk;
        const int rem0 = row0 % (QP * SNUM);
        const int qp0 = rem0 >> 4, s0 = rem0 & 15;
        const int rem1 = (row0 + 1) % (QP * SNUM);
        const int qp1 = rem1 >> 4, s1 = rem1 & 15;

        for (int t = tid; t < 2 * QQ; t += NTHR) {
            const int p = t / QQ;                 // 0 or 1
            const int q = t - p * QQ;
            const int qp_p = p ? qp1 : qp0;
            if (rls[q] != qp_p) continue;
            const int s_p = p ? s1 : s0;

            float spx, spy;
            poly_xy(rp + ((size_t)bC * QQ + q) * 8, s_p, spx, spy);
            const float4 off = p ? off1 : off0;
            float4 v;
            v.x = off.x + spx;
            v.y = off.y + spy;
            v.z = off.z + spx;
            v.w = off.w + spy;
            reinterpret_cast<float4*>(out)[((size_t)bC * QQ + q) * SNUM + s_p] = v;
        }
    }
}

extern "C" void kernel_launch(void* const* d_in, const int* in_sizes, int n_in,
                              void* d_out, int out_size) {
    const float* ref_polys = (const float*)d_in[0];
    const float* memory    = (const float*)d_in[1];
    const float* w1        = (const float*)d_in[2];
    const float* b1        = (const float*)d_in[3];
    const float* w2        = (const float*)d_in[4];
    const float* b2        = (const float*)d_in[5];
    const int*   ref_lvls  = (const int*)d_in[6];
    float* out = (float*)d_out;

    fused_kernel<<<NBLK, NTHR>>>(ref_polys, memory, w1, b1, w2, b2, ref_lvls, out);
}

// round 10
// speedup vs baseline: 1.5305x; 1.5305x over previous
#include <cuda_runtime.h>

#define BB 16
#define QQ 300
#define SNUM 16
#define HID 256
#define T_TOT 13125
#define W0 100
#define H0 100
#define QP 3
#define S_SCALE_C 0.077f
#define RB 2
#define NBLK1 (BB * QP * SNUM / RB)   // 384

// scratch: pre-scaled tanh offsets for the 768 distinct (b, q', s) rows, 4 values each
__device__ __align__(16) float g_off[BB * QP * SNUM * 4];

typedef unsigned long long ull;

__device__ __forceinline__ ull pack2(float lo, float hi) {
    ull r; asm("mov.b64 %0, {%1, %2};" : "=l"(r) : "f"(lo), "f"(hi)); return r;
}
__device__ __forceinline__ void unpack2(ull v, float& lo, float& hi) {
    asm("mov.b64 {%0, %1}, %2;" : "=f"(lo), "=f"(hi) : "l"(v));
}
__device__ __forceinline__ void fma2(ull& d, ull a, ull b) {
    asm("fma.rn.f32x2 %0, %1, %2, %3;" : "=l"(d) : "l"(a), "l"(b), "l"(d));
}
__device__ __forceinline__ float tanh_fast(float x) {
    float r; asm("tanh.approx.f32 %0, %1;" : "=f"(r) : "f"(x)); return r;
}

__device__ __forceinline__ void poly_xy(const float* __restrict__ c, int s,
                                        float& spx, float& spy) {
    const float t  = (float)s * (1.0f / (float)(SNUM - 1));
    const float t2 = t * t, t3 = t2 * t;
    spx = 2.0f * (c[0] * t3 + c[1] * t2 + c[2] * t + c[3] - 0.5f);
    spy = 2.0f * (c[4] * t3 + c[5] * t2 + c[6] * t + c[7] - 0.5f);
}

// Kernel 1: 2 rows per block; bilinear sample + 2-layer MLP head, f32x2-packed.
__global__ __launch_bounds__(HID) void sample_mlp_kernel(
        const float* __restrict__ rp,
        const float* __restrict__ mem,
        const float* __restrict__ w1,
        const float* __restrict__ b1,
        const float* __restrict__ w2,
        const float* __restrict__ b2) {
    const int blk = blockIdx.x;
    const int tid = threadIdx.x;

    __shared__ __align__(8) float gs[HID * RB];   // [c][r]
    __shared__ float h1s[RB * HID];               // [r][o]

    // ---- gather: 512 (c,r) entries, 2 per thread ----
    #pragma unroll
    for (int it = 0; it < RB; it++) {
        const int e = it * HID + tid;
        const int c = e & (HID - 1);
        const int r = e >> 8;                  // 0..1
        const int row = blk * RB + r;          // b*48 + qp*16 + s
        const int s  = row & 15;
        const int qp = (row >> 4) % QP;
        const int b  = row / (QP * SNUM);

        float gx, gy;
        poly_xy(rp + ((size_t)b * QQ + qp) * 8, s, gx, gy);
        const float x = (gx + 1.0f) * (W0 * 0.5f) - 0.5f;
        const float y = (gy + 1.0f) * (H0 * 0.5f) - 0.5f;
        const float x0f = floorf(x), y0f = floorf(y);
        const int x0 = (int)x0f, y0 = (int)y0f;
        const float wx1 = x - x0f, wx0 = 1.0f - wx1;
        const float wy1 = y - y0f, wy0 = 1.0f - wy1;

        const float* memb = mem + (size_t)b * T_TOT * HID + c;
        float a = 0.0f;
        #pragma unroll
        for (int dy = 0; dy < 2; dy++) {
            const int yi = y0 + dy;
            if (yi < 0 || yi >= H0) continue;
            const float wy = dy ? wy1 : wy0;
            #pragma unroll
            for (int dx = 0; dx < 2; dx++) {
                const int xi = x0 + dx;
                if (xi < 0 || xi >= W0) continue;
                a += wy * (dx ? wx1 : wx0) *
                     __ldg(memb + (size_t)(yi * W0 + xi) * HID);
            }
        }
        gs[c * RB + r] = a;
    }
    __syncthreads();

    // ---- layer 1: thread = output o; one f32x2 accumulator holds both rows ----
    {
        const float bv = __ldg(&b1[tid]);
        ull acc = pack2(bv, bv);
        const float* wc = w1 + tid;
        #pragma unroll 8
        for (int c = 0; c < HID; c++) {
            const float w = __ldg(wc + (size_t)c * HID);
            fma2(acc, *reinterpret_cast<const ull*>(&gs[c * RB]), pack2(w, w));
        }
        float v0, v1;
        unpack2(acc, v0, v1);
        h1s[0 * HID + tid] = tanh_fast(v0);
        h1s[1 * HID + tid] = tanh_fast(v1);
    }
    __syncthreads();

    // ---- layer 2: 8 warps = 2 rows x 4 outputs ----
    {
        const int wid = tid >> 5, lane = tid & 31;
        const int p = wid >> 2, k = wid & 3;
        float a = 0.0f;
        #pragma unroll
        for (int j = lane; j < HID; j += 32)
            a += h1s[p * HID + j] * __ldg(&w2[j * 4 + k]);
        #pragma unroll
        for (int o = 16; o > 0; o >>= 1)
            a += __shfl_xor_sync(0xffffffffu, a, o);
        if (lane == 0)
            g_off[(blk * RB + p) * 4 + k] = S_SCALE_C * tanh_fast(a + __ldg(&b2[k]));
    }
}

// Kernel 2: per (b,q,s) evaluate the cubic, gather scratch offsets by ref_level.
// (R1 version verbatim — measured 4.6us, every "improvement" regressed it.)
__global__ void out_kernel(const float* __restrict__ rp,
                           const int* __restrict__ rl,
                           float* __restrict__ out) {
    int idx = blockIdx.x * blockDim.x + threadIdx.x;   // b*Q*S + q*S + s
    if (idx >= BB * QQ * SNUM) return;
    int s = idx % SNUM;
    int q = (idx / SNUM) % QQ;
    int b = idx / (SNUM * QQ);

    const float* rpq = rp + ((size_t)b * QQ + q) * 8;
    float t  = (float)s * (1.0f / (float)(SNUM - 1));
    float t2 = t * t, t3 = t2 * t;
    float spx = 2.0f * (rpq[0] * t3 + rpq[1] * t2 + rpq[2] * t + rpq[3] - 0.5f);
    float spy = 2.0f * (rpq[4] * t3 + rpq[5] * t2 + rpq[6] * t + rpq[7] - 0.5f);

    int lvl = rl[b * QQ + q];                           // in {0,1,2}
    const float* off = g_off + (((size_t)b * QP + lvl) * SNUM + s) * 4;
    float4 v;
    v.x = off[0] + spx;
    v.y = off[1] + spy;
    v.z = off[2] + spx;
    v.w = off[3] + spy;
    reinterpret_cast<float4*>(out)[idx] = v;
}

extern "C" void kernel_launch(void* const* d_in, const int* in_sizes, int n_in,
                              void* d_out, int out_size) {
    const float* ref_polys = (const float*)d_in[0];
    const float* memory    = (const float*)d_in[1];
    const float* w1        = (const float*)d_in[2];
    const float* b1        = (const float*)d_in[3];
    const float* w2        = (const float*)d_in[4];
    const float* b2        = (const float*)d_in[5];
    const int*   ref_lvls  = (const int*)d_in[6];
    float* out = (float*)d_out;

    sample_mlp_kernel<<<NBLK1, HID>>>(ref_polys, memory, w1, b1, w2, b2);

    int total = BB * QQ * SNUM;
    out_kernel<<<(total + 255) / 256, 256>>>(ref_polys, ref_lvls, out);
}